// round 15
// baseline (speedup 1.0000x reference)
#include <cuda_runtime.h>
#include <cuda_bf16.h>
#include <math.h>
#include <stdint.h>

#define Bn 32
#define Cn 256
#define Hn 56
#define Wn 56
#define HWn 3136
#define Gn 4
#define Kn 7
#define CRn 64
#define KKn 49
#define PAD 3
#define TW 62
#define TPV 64

// Scratch (device globals)
__device__ float g_pooled[Bn*Cn];
__device__ float g_wk[Bn*Cn*KKn];
__device__ __align__(16) __nv_bfloat16 g_thi[(size_t)Bn*Cn*HWn];   // gelu(dwconv) hi plane
__device__ __align__(16) __nv_bfloat16 g_tlo[(size_t)Bn*Cn*HWn];   // lo plane
__device__ __align__(16) __nv_bfloat16 g_WH[Cn*Cn];                // pw_w hi, [n][k]
__device__ __align__(16) __nv_bfloat16 g_WL[Cn*Cn];                // pw_w lo

__device__ __forceinline__ float gelu_exact(float x) {
    return 0.5f * x * (1.0f + erff(x * 0.7071067811865475f));
}

// ---------------------------------------------------------------------------
// Kernel 1: pooled[b,c] = mean over H*W of r
// ---------------------------------------------------------------------------
__global__ void pool_kernel(const float* __restrict__ r) {
    int bc = blockIdx.x;
    const float4* p = reinterpret_cast<const float4*>(r + (size_t)bc * HWn);
    float sum = 0.f;
    for (int i = threadIdx.x; i < HWn / 4; i += blockDim.x) {
        float4 v = p[i];
        sum += (v.x + v.y) + (v.z + v.w);
    }
    __shared__ float red[8];
    #pragma unroll
    for (int o = 16; o > 0; o >>= 1) sum += __shfl_down_sync(0xffffffffu, sum, o);
    if ((threadIdx.x & 31) == 0) red[threadIdx.x >> 5] = sum;
    __syncthreads();
    if (threadIdx.x == 0) {
        float t = 0.f;
        for (int i = 0; i < (int)(blockDim.x >> 5); i++) t += red[i];
        g_pooled[bc] = t * (1.0f / (float)HWn);
    }
}

// ---------------------------------------------------------------------------
// Kernel 2: per-batch MLP -> alpha/beta -> summed dynamic kernel wk[b,c,49]
// ---------------------------------------------------------------------------
__global__ void wgen_kernel(const float* __restrict__ w1, const float* __restrict__ b1,
                            const float* __restrict__ w2, const float* __restrict__ b2,
                            const float* __restrict__ weight, const float* __restrict__ beta_scale) {
    int b = blockIdx.x;
    int tid = threadIdx.x;
    __shared__ float pooled[Cn];
    __shared__ float h[CRn];
    __shared__ float s0[Gn][Cn];
    __shared__ float s1[Gn][Cn];
    __shared__ float alpha[Gn][Cn];
    __shared__ float betasum[Cn];

    pooled[tid] = g_pooled[b * Cn + tid];
    __syncthreads();

    if (tid < CRn) {
        float acc = b1[tid];
        const float* wr = w1 + tid * Cn;
        #pragma unroll 4
        for (int k = 0; k < Cn; k++) acc += wr[k] * pooled[k];
        h[tid] = gelu_exact(acc);
    }
    __syncthreads();

    for (int o = tid; o < Cn * Gn * 2; o += blockDim.x) {
        float acc = b2[o];
        const float* wr = w2 + o * CRn;
        #pragma unroll
        for (int k = 0; k < CRn; k++) acc += wr[k] * h[k];
        int t = o & 1;
        int c = (o >> 1) & (Cn - 1);
        int g = o >> 9;
        if (t == 0) s0[g][c] = acc; else s1[g][c] = acc;
    }
    __syncthreads();

    if (tid < Cn) {
        int c = tid;
        float m = s0[0][c];
        #pragma unroll
        for (int g = 1; g < Gn; g++) m = fmaxf(m, s0[g][c]);
        float e[Gn], den = 0.f;
        #pragma unroll
        for (int g = 0; g < Gn; g++) { e[g] = expf(s0[g][c] - m); den += e[g]; }
        float inv = 1.0f / den;
        float bs = 0.f;
        #pragma unroll
        for (int g = 0; g < Gn; g++) {
            alpha[g][c] = e[g] * inv;
            bs += tanhf(s1[g][c] * expf(beta_scale[g * Cn + c]) * 0.1f);
        }
        betasum[c] = bs;
    }
    __syncthreads();

    for (int i = tid; i < Cn * KKn; i += blockDim.x) {
        int c = i / KKn;
        int kk = i - c * KKn;
        float acc = betasum[c];
        #pragma unroll
        for (int g = 0; g < Gn; g++)
            acc += alpha[g][c] * weight[(g * Cn + c) * KKn + kk];
        g_wk[(b * Cn + c) * KKn + kk] = acc;
    }
}

// ---------------------------------------------------------------------------
// Kernel 2.5: split pw_w into bf16 hi/lo planes, [n][k] row-major
// ---------------------------------------------------------------------------
__global__ void bprep_kernel(const float* __restrict__ pw_w) {
    int idx = blockIdx.x * 256 + threadIdx.x;   // n*256 + k
    float v = pw_w[idx];
    __nv_bfloat16 hb = __float2bfloat16(v);
    g_WH[idx] = hb;
    g_WL[idx] = __float2bfloat16(v - __bfloat162float(hb));
}

// ---------------------------------------------------------------------------
// Kernel 3: depthwise 7x7 + exact GELU -> separate bf16 hi/lo planes
// 224 threads, vertical-strip mapping (no launch_bounds: 32-reg/92%-occ form).
// ---------------------------------------------------------------------------
__global__ void dwconv_kernel(const float* __restrict__ s) {
    int bc = blockIdx.x;
    __shared__ float tile[TW * TPV];
    __shared__ float wkS[KKn];
    const float* sp = s + (size_t)bc * HWn;
    int tid = threadIdx.x;
    int wid = tid >> 5, lane = tid & 31;

    if (tid < KKn) wkS[tid] = g_wk[bc * KKn + tid];

    for (int row = wid; row < TW; row += 7) {
        int y = row - PAD;
        float* trow = &tile[row * TPV];
        if (y >= 0 && y < Hn) {
            const float* srow = sp + y * Wn;
            #pragma unroll
            for (int xcol = lane; xcol < TW; xcol += 32) {
                int xx = xcol - PAD;
                trow[xcol] = (xx >= 0 && xx < Wn) ? srow[xx] : 0.f;
            }
        } else {
            #pragma unroll
            for (int xcol = lane; xcol < TW; xcol += 32) trow[xcol] = 0.f;
        }
    }
    __syncthreads();

    int g  = tid / 56;
    int x  = tid - g * 56;
    int ys = g * 14;

    float w[KKn];
    #pragma unroll
    for (int i = 0; i < KKn; i++) w[i] = wkS[i];

    float acc[14];
    #pragma unroll
    for (int i = 0; i < 14; i++) acc[i] = 0.f;

    const float* basep = &tile[ys * TPV + x];
    #pragma unroll
    for (int rr = 0; rr < 20; rr++) {
        float v[Kn];
        #pragma unroll
        for (int kx = 0; kx < Kn; kx++) v[kx] = basep[rr * TPV + kx];
        #pragma unroll
        for (int ky = 0; ky < Kn; ky++) {
            int i = rr - ky;
            if (i >= 0 && i < 14) {
                #pragma unroll
                for (int kx = 0; kx < Kn; kx++)
                    acc[i] = fmaf(w[ky * Kn + kx], v[kx], acc[i]);
            }
        }
    }

    size_t ob = (size_t)bc * HWn + ys * Wn + x;
    #pragma unroll
    for (int i = 0; i < 14; i++) {
        float vv = gelu_exact(acc[i]);
        __nv_bfloat16 hb = __float2bfloat16(vv);
        g_thi[ob + i * Wn] = hb;
        g_tlo[ob + i * Wn] = __float2bfloat16(vv - __bfloat162float(hb));
    }
}

// ---------------------------------------------------------------------------
// Kernel 4: pointwise conv = GEMM via bf16-split mma.sync
// Both loaders now pure 16B LDG -> 16B STS (A from g_thi/g_tlo planes,
// W from g_WH/g_WL). No cvt/PRMT in the loop. Reg-staged double buffer.
// Block 64m x 128n, BK=32, 8 warps (32m x 32n).
// ---------------------------------------------------------------------------
#define BM 64
#define BN 128
#define BK 32
#define APAD 72
#define WPAD 40

#define MMA_BF16(d, a, b0v, b1v) \
    asm volatile("mma.sync.aligned.m16n8k16.row.col.f32.bf16.bf16.f32 " \
        "{%0,%1,%2,%3}, {%4,%5,%6,%7}, {%8,%9}, {%0,%1,%2,%3};" \
        : "+f"(d[0]), "+f"(d[1]), "+f"(d[2]), "+f"(d[3]) \
        : "r"(a[0]), "r"(a[1]), "r"(a[2]), "r"(a[3]), "r"(b0v), "r"(b1v))

#define LDSM_T(dst, addr) \
    asm volatile("ldmatrix.sync.aligned.m8n8.x4.trans.shared.b16 {%0,%1,%2,%3}, [%4];" \
        : "=r"(dst[0]), "=r"(dst[1]), "=r"(dst[2]), "=r"(dst[3]) : "r"(addr))
#define LDSM_N(d0v, d1v, d2v, d3v, addr) \
    asm volatile("ldmatrix.sync.aligned.m8n8.x4.shared.b16 {%0,%1,%2,%3}, [%4];" \
        : "=r"(d0v), "=r"(d1v), "=r"(d2v), "=r"(d3v) : "r"(addr))

__global__ __launch_bounds__(256, 2)
void pw_kernel(const float* __restrict__ pw_b, float* __restrict__ out) {
    __shared__ __align__(16) __nv_bfloat16 AH[2][BK][APAD];
    __shared__ __align__(16) __nv_bfloat16 AL[2][BK][APAD];
    __shared__ __align__(16) __nv_bfloat16 WH[2][BN][WPAD];
    __shared__ __align__(16) __nv_bfloat16 WL[2][BN][WPAD];
    __shared__ float biasS[BN];

    int tid = threadIdx.x;
    int hw0 = blockIdx.x * BM;
    int d0  = blockIdx.y * BN;
    int b   = blockIdx.z;

    if (tid < BN) biasS[tid] = pw_b[d0 + tid];

    int warp = tid >> 5, lane = tid & 31;
    int wm = warp & 1;
    int wn = warp >> 1;

    float acc[2][4][4];
    #pragma unroll
    for (int i = 0; i < 2; i++)
        #pragma unroll
        for (int j = 0; j < 4; j++)
            #pragma unroll
            for (int k = 0; k < 4; k++) acc[i][j][k] = 0.f;

    int l_b = lane >> 3;
    int l_r = lane & 7;
    int a_krow = ((l_b >> 1) << 3) + l_r;
    int a_mcol = ((l_b & 1) << 3);
    int b_nrow = ((l_b >> 1) << 3) + l_r;
    int b_kcol = ((l_b & 1) << 3);

    // A loader: 512 16B-chunks/stage: id = tid + j*256; pl=id>>8, kc=(id>>3)&31, cc=id&7
    const __nv_bfloat16* thi_b = g_thi + (size_t)b * Cn * HWn + hw0;
    const __nv_bfloat16* tlo_b = g_tlo + (size_t)b * Cn * HWn + hw0;
    // W loader: 1024 16B-chunks/stage: id = tid + j*256; pl=id>>9, dd=(id>>2)&127, cc=id&3
    uint4 aReg[2];
    uint4 wReg[4];

    {
        #pragma unroll
        for (int j = 0; j < 2; j++) {
            int id = tid + j * 256;
            int pl = id >> 8, kc = (id >> 3) & 31, cc = id & 7;
            const __nv_bfloat16* src = (pl ? tlo_b : thi_b) + (size_t)kc * HWn + cc * 8;
            aReg[j] = *reinterpret_cast<const uint4*>(src);
        }
        #pragma unroll
        for (int j = 0; j < 4; j++) {
            int id = tid + j * 256;
            int pl = id >> 9, dd = (id >> 2) & 127, cc = id & 3;
            const __nv_bfloat16* src = (pl ? g_WL : g_WH) + (size_t)(d0 + dd) * Cn + cc * 8;
            wReg[j] = *reinterpret_cast<const uint4*>(src);
        }
        #pragma unroll
        for (int j = 0; j < 2; j++) {
            int id = tid + j * 256;
            int pl = id >> 8, kc = (id >> 3) & 31, cc = id & 7;
            __nv_bfloat16* dst = (pl ? &AL[0][kc][cc * 8] : &AH[0][kc][cc * 8]);
            *reinterpret_cast<uint4*>(dst) = aReg[j];
        }
        #pragma unroll
        for (int j = 0; j < 4; j++) {
            int id = tid + j * 256;
            int pl = id >> 9, dd = (id >> 2) & 127, cc = id & 3;
            __nv_bfloat16* dst = (pl ? &WL[0][dd][cc * 8] : &WH[0][dd][cc * 8]);
            *reinterpret_cast<uint4*>(dst) = wReg[j];
        }
    }
    __syncthreads();

    #pragma unroll 1
    for (int st = 0; st < 8; st++) {
        int cur = st & 1;
        int nxt = cur ^ 1;

        if (st < 7) {
            int c0 = (st + 1) * BK;
            #pragma unroll
            for (int j = 0; j < 2; j++) {
                int id = tid + j * 256;
                int pl = id >> 8, kc = (id >> 3) & 31, cc = id & 7;
                const __nv_bfloat16* src = (pl ? tlo_b : thi_b) + (size_t)(c0 + kc) * HWn + cc * 8;
                aReg[j] = *reinterpret_cast<const uint4*>(src);
            }
            #pragma unroll
            for (int j = 0; j < 4; j++) {
                int id = tid + j * 256;
                int pl = id >> 9, dd = (id >> 2) & 127, cc = id & 3;
                const __nv_bfloat16* src = (pl ? g_WL : g_WH) + (size_t)(d0 + dd) * Cn + c0 + cc * 8;
                wReg[j] = *reinterpret_cast<const uint4*>(src);
            }
        }

        #pragma unroll
        for (int kk = 0; kk < BK; kk += 16) {
            uint32_t ah[2][4], al[2][4];
            #pragma unroll
            for (int mt = 0; mt < 2; mt++) {
                int m_col = wm * 32 + mt * 16 + a_mcol;
                int k_row = kk + a_krow;
                LDSM_T(ah[mt], (uint32_t)__cvta_generic_to_shared(&AH[cur][k_row][m_col]));
                LDSM_T(al[mt], (uint32_t)__cvta_generic_to_shared(&AL[cur][k_row][m_col]));
            }
            uint32_t bh[8], bl[8];
            #pragma unroll
            for (int nh = 0; nh < 2; nh++) {
                int nrow = wn * 32 + nh * 16 + b_nrow;
                int k_col = kk + b_kcol;
                LDSM_N(bh[nh*4+0], bh[nh*4+1], bh[nh*4+2], bh[nh*4+3],
                       (uint32_t)__cvta_generic_to_shared(&WH[cur][nrow][k_col]));
                LDSM_N(bl[nh*4+0], bl[nh*4+1], bl[nh*4+2], bl[nh*4+3],
                       (uint32_t)__cvta_generic_to_shared(&WL[cur][nrow][k_col]));
            }
            #pragma unroll
            for (int mt = 0; mt < 2; mt++) {
                #pragma unroll
                for (int nt = 0; nt < 4; nt++) {
                    MMA_BF16(acc[mt][nt], ah[mt], bh[nt*2], bh[nt*2+1]);
                    MMA_BF16(acc[mt][nt], ah[mt], bl[nt*2], bl[nt*2+1]);
                    MMA_BF16(acc[mt][nt], al[mt], bh[nt*2], bh[nt*2+1]);
                }
            }
        }

        if (st < 7) {
            #pragma unroll
            for (int j = 0; j < 2; j++) {
                int id = tid + j * 256;
                int pl = id >> 8, kc = (id >> 3) & 31, cc = id & 7;
                __nv_bfloat16* dst = (pl ? &AL[nxt][kc][cc * 8] : &AH[nxt][kc][cc * 8]);
                *reinterpret_cast<uint4*>(dst) = aReg[j];
            }
            #pragma unroll
            for (int j = 0; j < 4; j++) {
                int id = tid + j * 256;
                int pl = id >> 9, dd = (id >> 2) & 127, cc = id & 3;
                __nv_bfloat16* dst = (pl ? &WL[nxt][dd][cc * 8] : &WH[nxt][dd][cc * 8]);
                *reinterpret_cast<uint4*>(dst) = wReg[j];
            }
        }
        __syncthreads();
    }

    #pragma unroll
    for (int mt = 0; mt < 2; mt++) {
        #pragma unroll
        for (int nt = 0; nt < 4; nt++) {
            int hw = hw0 + wm * 32 + mt * 16 + (lane >> 2);
            int dl = wn * 32 + nt * 8 + (lane & 3) * 2;
            float* o = out + ((size_t)b * Cn + (d0 + dl)) * HWn + hw;
            float b0v = biasS[dl], b1v = biasS[dl + 1];
            o[0]       = acc[mt][nt][0] + b0v;
            o[HWn]     = acc[mt][nt][1] + b1v;
            o[8]       = acc[mt][nt][2] + b0v;
            o[HWn + 8] = acc[mt][nt][3] + b1v;
        }
    }
}

// ---------------------------------------------------------------------------
extern "C" void kernel_launch(void* const* d_in, const int* in_sizes, int n_in,
                              void* d_out, int out_size) {
    const float* s        = (const float*)d_in[0];
    const float* r        = (const float*)d_in[1];
    const float* proj_w1  = (const float*)d_in[2];
    const float* proj_b1  = (const float*)d_in[3];
    const float* proj_w2  = (const float*)d_in[4];
    const float* proj_b2  = (const float*)d_in[5];
    const float* weight   = (const float*)d_in[6];
    const float* beta_sc  = (const float*)d_in[7];
    const float* pw_w     = (const float*)d_in[8];
    const float* pw_b     = (const float*)d_in[9];
    float* out = (float*)d_out;

    pool_kernel<<<Bn * Cn, 256>>>(r);
    wgen_kernel<<<Bn, 256>>>(proj_w1, proj_b1, proj_w2, proj_b2, weight, beta_sc);
    bprep_kernel<<<Cn, 256>>>(pw_w);
    dwconv_kernel<<<Bn * Cn, 224>>>(s);
    pw_kernel<<<dim3(HWn / BM, Cn / BN, Bn), 256>>>(pw_b, out);
}

// round 16
// speedup vs baseline: 1.1052x; 1.1052x over previous
#include <cuda_runtime.h>
#include <cuda_fp16.h>
#include <math.h>
#include <stdint.h>

#define Bn 32
#define Cn 256
#define Hn 56
#define Wn 56
#define HWn 3136
#define Gn 4
#define Kn 7
#define CRn 64
#define KKn 49
#define PAD 3
#define TW 62
#define TPV 64

// Scratch (device globals)
__device__ float g_pooled[Bn*Cn];
__device__ float g_wk[Bn*Cn*KKn];
__device__ uint32_t g_t[(size_t)Bn*Cn*HWn];        // packed (fp16 hi | fp16 lo<<16), [b][c][hw]
__device__ __align__(16) __half g_WH[Cn*Cn];       // pw_w fp16, [n][k] row-major

__device__ __forceinline__ float gelu_exact(float x) {
    return 0.5f * x * (1.0f + erff(x * 0.7071067811865475f));
}

__device__ __forceinline__ uint32_t prmt(uint32_t a, uint32_t b, uint32_t s) {
    uint32_t d;
    asm("prmt.b32 %0,%1,%2,%3;" : "=r"(d) : "r"(a), "r"(b), "r"(s));
    return d;
}

// ---------------------------------------------------------------------------
// Kernel 1: pooled[b,c] = mean over H*W of r
// ---------------------------------------------------------------------------
__global__ void pool_kernel(const float* __restrict__ r) {
    int bc = blockIdx.x;
    const float4* p = reinterpret_cast<const float4*>(r + (size_t)bc * HWn);
    float sum = 0.f;
    for (int i = threadIdx.x; i < HWn / 4; i += blockDim.x) {
        float4 v = p[i];
        sum += (v.x + v.y) + (v.z + v.w);
    }
    __shared__ float red[8];
    #pragma unroll
    for (int o = 16; o > 0; o >>= 1) sum += __shfl_down_sync(0xffffffffu, sum, o);
    if ((threadIdx.x & 31) == 0) red[threadIdx.x >> 5] = sum;
    __syncthreads();
    if (threadIdx.x == 0) {
        float t = 0.f;
        for (int i = 0; i < (int)(blockDim.x >> 5); i++) t += red[i];
        g_pooled[bc] = t * (1.0f / (float)HWn);
    }
}

// ---------------------------------------------------------------------------
// Kernel 2: per-batch MLP -> alpha/beta -> summed dynamic kernel wk[b,c,49]
// ---------------------------------------------------------------------------
__global__ void wgen_kernel(const float* __restrict__ w1, const float* __restrict__ b1,
                            const float* __restrict__ w2, const float* __restrict__ b2,
                            const float* __restrict__ weight, const float* __restrict__ beta_scale) {
    int b = blockIdx.x;
    int tid = threadIdx.x;
    __shared__ float pooled[Cn];
    __shared__ float h[CRn];
    __shared__ float s0[Gn][Cn];
    __shared__ float s1[Gn][Cn];
    __shared__ float alpha[Gn][Cn];
    __shared__ float betasum[Cn];

    pooled[tid] = g_pooled[b * Cn + tid];
    __syncthreads();

    if (tid < CRn) {
        float acc = b1[tid];
        const float* wr = w1 + tid * Cn;
        #pragma unroll 4
        for (int k = 0; k < Cn; k++) acc += wr[k] * pooled[k];
        h[tid] = gelu_exact(acc);
    }
    __syncthreads();

    for (int o = tid; o < Cn * Gn * 2; o += blockDim.x) {
        float acc = b2[o];
        const float* wr = w2 + o * CRn;
        #pragma unroll
        for (int k = 0; k < CRn; k++) acc += wr[k] * h[k];
        int t = o & 1;
        int c = (o >> 1) & (Cn - 1);
        int g = o >> 9;
        if (t == 0) s0[g][c] = acc; else s1[g][c] = acc;
    }
    __syncthreads();

    if (tid < Cn) {
        int c = tid;
        float m = s0[0][c];
        #pragma unroll
        for (int g = 1; g < Gn; g++) m = fmaxf(m, s0[g][c]);
        float e[Gn], den = 0.f;
        #pragma unroll
        for (int g = 0; g < Gn; g++) { e[g] = expf(s0[g][c] - m); den += e[g]; }
        float inv = 1.0f / den;
        float bs = 0.f;
        #pragma unroll
        for (int g = 0; g < Gn; g++) {
            alpha[g][c] = e[g] * inv;
            bs += tanhf(s1[g][c] * expf(beta_scale[g * Cn + c]) * 0.1f);
        }
        betasum[c] = bs;
    }
    __syncthreads();

    for (int i = tid; i < Cn * KKn; i += blockDim.x) {
        int c = i / KKn;
        int kk = i - c * KKn;
        float acc = betasum[c];
        #pragma unroll
        for (int g = 0; g < Gn; g++)
            acc += alpha[g][c] * weight[(g * Cn + c) * KKn + kk];
        g_wk[(b * Cn + c) * KKn + kk] = acc;
    }
}

// ---------------------------------------------------------------------------
// Kernel 2.5: round pw_w to fp16, [n][k] row-major (single plane)
// ---------------------------------------------------------------------------
__global__ void bprep_kernel(const float* __restrict__ pw_w) {
    int idx = blockIdx.x * 256 + threadIdx.x;   // n*256 + k
    g_WH[idx] = __float2half_rn(pw_w[idx]);
}

// ---------------------------------------------------------------------------
// Kernel 3: depthwise 7x7 + exact GELU -> packed fp16 hi/lo (one uint32/elem)
// 224 threads, vertical-strip mapping (R13 config: no launch_bounds cap).
// ---------------------------------------------------------------------------
__global__ void dwconv_kernel(const float* __restrict__ s) {
    int bc = blockIdx.x;
    __shared__ float tile[TW * TPV];
    __shared__ float wkS[KKn];
    const float* sp = s + (size_t)bc * HWn;
    int tid = threadIdx.x;
    int wid = tid >> 5, lane = tid & 31;

    if (tid < KKn) wkS[tid] = g_wk[bc * KKn + tid];

    for (int row = wid; row < TW; row += 7) {
        int y = row - PAD;
        float* trow = &tile[row * TPV];
        if (y >= 0 && y < Hn) {
            const float* srow = sp + y * Wn;
            #pragma unroll
            for (int xcol = lane; xcol < TW; xcol += 32) {
                int xx = xcol - PAD;
                trow[xcol] = (xx >= 0 && xx < Wn) ? srow[xx] : 0.f;
            }
        } else {
            #pragma unroll
            for (int xcol = lane; xcol < TW; xcol += 32) trow[xcol] = 0.f;
        }
    }
    __syncthreads();

    int g  = tid / 56;
    int x  = tid - g * 56;
    int ys = g * 14;

    float w[KKn];
    #pragma unroll
    for (int i = 0; i < KKn; i++) w[i] = wkS[i];

    float acc[14];
    #pragma unroll
    for (int i = 0; i < 14; i++) acc[i] = 0.f;

    const float* basep = &tile[ys * TPV + x];
    #pragma unroll
    for (int rr = 0; rr < 20; rr++) {
        float v[Kn];
        #pragma unroll
        for (int kx = 0; kx < Kn; kx++) v[kx] = basep[rr * TPV + kx];
        #pragma unroll
        for (int ky = 0; ky < Kn; ky++) {
            int i = rr - ky;
            if (i >= 0 && i < 14) {
                #pragma unroll
                for (int kx = 0; kx < Kn; kx++)
                    acc[i] = fmaf(w[ky * Kn + kx], v[kx], acc[i]);
            }
        }
    }

    uint32_t* outp = g_t + (size_t)bc * HWn + ys * Wn + x;
    #pragma unroll
    for (int i = 0; i < 14; i++) {
        float vv = gelu_exact(acc[i]);
        __half hb = __float2half_rn(vv);
        float lo = vv - __half2float(hb);
        __half lb = __float2half_rn(lo);
        uint32_t word = (uint32_t)__half_as_ushort(hb)
                      | ((uint32_t)__half_as_ushort(lb) << 16);
        outp[i * Wn] = word;
    }
}

// ---------------------------------------------------------------------------
// Kernel 4: pointwise conv = GEMM via fp16 A-split mma.sync (2 MMAs/term)
// D[m=hw][n=d] = (Ah+Al)[m][k] * W[k][n];  A = t packed hi|lo ([k][m],
// ldmatrix.trans after PRMT de-interleave), W = single fp16 plane ([n][k]).
// Block 64m x 128n, BK=32, 8 warps (32m x 32n), reg-staged double buffer.
// ---------------------------------------------------------------------------
#define BM 64
#define BN 128
#define BK 32
#define APAD 72
#define WPAD 40

#define MMA_F16(d, a, b0v, b1v) \
    asm volatile("mma.sync.aligned.m16n8k16.row.col.f32.f16.f16.f32 " \
        "{%0,%1,%2,%3}, {%4,%5,%6,%7}, {%8,%9}, {%0,%1,%2,%3};" \
        : "+f"(d[0]), "+f"(d[1]), "+f"(d[2]), "+f"(d[3]) \
        : "r"(a[0]), "r"(a[1]), "r"(a[2]), "r"(a[3]), "r"(b0v), "r"(b1v))

#define LDSM_T(dst, addr) \
    asm volatile("ldmatrix.sync.aligned.m8n8.x4.trans.shared.b16 {%0,%1,%2,%3}, [%4];" \
        : "=r"(dst[0]), "=r"(dst[1]), "=r"(dst[2]), "=r"(dst[3]) : "r"(addr))
#define LDSM_N(d0v, d1v, d2v, d3v, addr) \
    asm volatile("ldmatrix.sync.aligned.m8n8.x4.shared.b16 {%0,%1,%2,%3}, [%4];" \
        : "=r"(d0v), "=r"(d1v), "=r"(d2v), "=r"(d3v) : "r"(addr))

__global__ __launch_bounds__(256, 2)
void pw_kernel(const float* __restrict__ pw_b, float* __restrict__ out) {
    __shared__ __align__(16) __half AH[2][BK][APAD];
    __shared__ __align__(16) __half AL[2][BK][APAD];
    __shared__ __align__(16) __half WS[2][BN][WPAD];
    __shared__ float biasS[BN];

    int tid = threadIdx.x;
    int hw0 = blockIdx.x * BM;
    int d0  = blockIdx.y * BN;
    int b   = blockIdx.z;

    if (tid < BN) biasS[tid] = pw_b[d0 + tid];

    int warp = tid >> 5, lane = tid & 31;
    int wm = warp & 1;
    int wn = warp >> 1;

    float acc[2][4][4];
    #pragma unroll
    for (int i = 0; i < 2; i++)
        #pragma unroll
        for (int j = 0; j < 4; j++)
            #pragma unroll
            for (int k = 0; k < 4; k++) acc[i][j][k] = 0.f;

    int l_b = lane >> 3;
    int l_r = lane & 7;
    int a_krow = ((l_b >> 1) << 3) + l_r;
    int a_mcol = ((l_b & 1) << 3);
    int b_nrow = ((l_b >> 1) << 3) + l_r;
    int b_kcol = ((l_b & 1) << 3);

    // A loader: kc = tid>>3 (0..31), mg = tid&7 (8 m-elems each)
    int kc = tid >> 3, mg = tid & 7;
    const uint32_t* tbase = g_t + (size_t)b * Cn * HWn + hw0 + mg * 8;
    // W loader: 512 16B-chunks/stage: id = tid + j*256 (j<2); dd = id>>2, cc = id&3
    uint4 aReg[2];
    uint4 wReg[2];

    {
        #pragma unroll
        for (int j = 0; j < 2; j++)
            aReg[j] = *reinterpret_cast<const uint4*>(tbase + (size_t)kc * HWn + j * 4);
        #pragma unroll
        for (int j = 0; j < 2; j++) {
            int id = tid + j * 256;
            int dd = id >> 2, cc = id & 3;
            wReg[j] = *reinterpret_cast<const uint4*>(g_WH + (size_t)(d0 + dd) * Cn + cc * 8);
        }
        #pragma unroll
        for (int j = 0; j < 2; j++) {
            uint2 hi = { prmt(aReg[j].x, aReg[j].y, 0x5410), prmt(aReg[j].z, aReg[j].w, 0x5410) };
            uint2 lo = { prmt(aReg[j].x, aReg[j].y, 0x7632), prmt(aReg[j].z, aReg[j].w, 0x7632) };
            *reinterpret_cast<uint2*>(&AH[0][kc][mg * 8 + j * 4]) = hi;
            *reinterpret_cast<uint2*>(&AL[0][kc][mg * 8 + j * 4]) = lo;
        }
        #pragma unroll
        for (int j = 0; j < 2; j++) {
            int id = tid + j * 256;
            int dd = id >> 2, cc = id & 3;
            *reinterpret_cast<uint4*>(&WS[0][dd][cc * 8]) = wReg[j];
        }
    }
    __syncthreads();

    #pragma unroll 1
    for (int st = 0; st < 8; st++) {
        int cur = st & 1;
        int nxt = cur ^ 1;

        if (st < 7) {
            int c0 = (st + 1) * BK;
            #pragma unroll
            for (int j = 0; j < 2; j++)
                aReg[j] = *reinterpret_cast<const uint4*>(tbase + (size_t)(c0 + kc) * HWn + j * 4);
            #pragma unroll
            for (int j = 0; j < 2; j++) {
                int id = tid + j * 256;
                int dd = id >> 2, cc = id & 3;
                wReg[j] = *reinterpret_cast<const uint4*>(g_WH + (size_t)(d0 + dd) * Cn + c0 + cc * 8);
            }
        }

        #pragma unroll
        for (int kk = 0; kk < BK; kk += 16) {
            uint32_t ah[2][4], al[2][4];
            #pragma unroll
            for (int mt = 0; mt < 2; mt++) {
                int m_col = wm * 32 + mt * 16 + a_mcol;
                int k_row = kk + a_krow;
                LDSM_T(ah[mt], (uint32_t)__cvta_generic_to_shared(&AH[cur][k_row][m_col]));
                LDSM_T(al[mt], (uint32_t)__cvta_generic_to_shared(&AL[cur][k_row][m_col]));
            }
            uint32_t bh[8];
            #pragma unroll
            for (int nh = 0; nh < 2; nh++) {
                int nrow = wn * 32 + nh * 16 + b_nrow;
                int k_col = kk + b_kcol;
                LDSM_N(bh[nh*4+0], bh[nh*4+1], bh[nh*4+2], bh[nh*4+3],
                       (uint32_t)__cvta_generic_to_shared(&WS[cur][nrow][k_col]));
            }
            #pragma unroll
            for (int mt = 0; mt < 2; mt++) {
                #pragma unroll
                for (int nt = 0; nt < 4; nt++) {
                    MMA_F16(acc[mt][nt], ah[mt], bh[nt*2], bh[nt*2+1]);
                    MMA_F16(acc[mt][nt], al[mt], bh[nt*2], bh[nt*2+1]);
                }
            }
        }

        if (st < 7) {
            #pragma unroll
            for (int j = 0; j < 2; j++) {
                uint2 hi = { prmt(aReg[j].x, aReg[j].y, 0x5410), prmt(aReg[j].z, aReg[j].w, 0x5410) };
                uint2 lo = { prmt(aReg[j].x, aReg[j].y, 0x7632), prmt(aReg[j].z, aReg[j].w, 0x7632) };
                *reinterpret_cast<uint2*>(&AH[nxt][kc][mg * 8 + j * 4]) = hi;
                *reinterpret_cast<uint2*>(&AL[nxt][kc][mg * 8 + j * 4]) = lo;
            }
            #pragma unroll
            for (int j = 0; j < 2; j++) {
                int id = tid + j * 256;
                int dd = id >> 2, cc = id & 3;
                *reinterpret_cast<uint4*>(&WS[nxt][dd][cc * 8]) = wReg[j];
            }
        }
        __syncthreads();
    }

    #pragma unroll
    for (int mt = 0; mt < 2; mt++) {
        #pragma unroll
        for (int nt = 0; nt < 4; nt++) {
            int hw = hw0 + wm * 32 + mt * 16 + (lane >> 2);
            int dl = wn * 32 + nt * 8 + (lane & 3) * 2;
            float* o = out + ((size_t)b * Cn + (d0 + dl)) * HWn + hw;
            float b0v = biasS[dl], b1v = biasS[dl + 1];
            o[0]       = acc[mt][nt][0] + b0v;
            o[HWn]     = acc[mt][nt][1] + b1v;
            o[8]       = acc[mt][nt][2] + b0v;
            o[HWn + 8] = acc[mt][nt][3] + b1v;
        }
    }
}

// ---------------------------------------------------------------------------
extern "C" void kernel_launch(void* const* d_in, const int* in_sizes, int n_in,
                              void* d_out, int out_size) {
    const float* s        = (const float*)d_in[0];
    const float* r        = (const float*)d_in[1];
    const float* proj_w1  = (const float*)d_in[2];
    const float* proj_b1  = (const float*)d_in[3];
    const float* proj_w2  = (const float*)d_in[4];
    const float* proj_b2  = (const float*)d_in[5];
    const float* weight   = (const float*)d_in[6];
    const float* beta_sc  = (const float*)d_in[7];
    const float* pw_w     = (const float*)d_in[8];
    const float* pw_b     = (const float*)d_in[9];
    float* out = (float*)d_out;

    pool_kernel<<<Bn * Cn, 256>>>(r);
    wgen_kernel<<<Bn, 256>>>(proj_w1, proj_b1, proj_w2, proj_b2, weight, beta_sc);
    bprep_kernel<<<Cn, 256>>>(pw_w);
    dwconv_kernel<<<Bn * Cn, 224>>>(s);
    pw_kernel<<<dim3(HWn / BM, Cn / BN, Bn), 256>>>(pw_b, out);
}